// round 8
// baseline (speedup 1.0000x reference)
#include <cuda_runtime.h>
#include <cstdint>

#define NMAX 100000
#define EMAX 1600000
#define HID 64
#define SCAN_B 1024

// ---------------- scratch (device globals; no allocation allowed) ----------------
__device__ __align__(256) int   g_cnt [NMAX];        // in-degree (excl. self loop)
__device__ __align__(256) int   g_fill[NMAX];        // bucket fill cursors
__device__ __align__(256) int   g_off [NMAX];        // CSR exclusive offsets
__device__ __align__(256) int   g_bsum[128];         // scan block sums
__device__ __align__(256) float g_dinv[NMAX];        // deg^-1/2 (incl. self loop)
__device__ __align__(256) int2  g_edge[EMAX];        // CSR: {src node, norm as bits}
__device__ __align__(256) float g_hw  [NMAX * HID];  // h @ W
__device__ __align__(256) float g_h   [NMAX * HID];  // layer activations

// ---------------- packed f32x2 helpers (sm_103a FFMA2 path) ----------------
__device__ __forceinline__ unsigned long long splat2(float a) {
    unsigned long long r;
    asm("mov.b64 %0, {%1, %1};" : "=l"(r) : "f"(a));
    return r;
}
__device__ __forceinline__ void fma2(unsigned long long& d,
                                     unsigned long long a, unsigned long long b) {
    asm("fma.rn.f32x2 %0, %1, %2, %0;" : "+l"(d) : "l"(a), "l"(b));
}
__device__ __forceinline__ void unpack2(unsigned long long v, float& lo, float& hi) {
    asm("mov.b64 {%0, %1}, %2;" : "=f"(lo), "=f"(hi) : "l"(v));
}

// ---------------- build: histogram / dinv ----------------
__global__ void k_zero(int* __restrict__ cnt, int* __restrict__ fill, int n) {
    int i = blockIdx.x * blockDim.x + threadIdx.x;
    if (i < n) { cnt[i] = 0; fill[i] = 0; }
}

// 4 edges per thread via int4 index reads
__global__ void k_hist(const int* __restrict__ col, int* __restrict__ cnt, int E) {
    int i = blockIdx.x * blockDim.x + threadIdx.x;
    int e0 = i * 4;
    if (e0 + 3 < E) {
        int4 c = *(const int4*)(col + e0);
        atomicAdd(&cnt[c.x], 1);
        atomicAdd(&cnt[c.y], 1);
        atomicAdd(&cnt[c.z], 1);
        atomicAdd(&cnt[c.w], 1);
    } else {
        for (int e = e0; e < E; e++) atomicAdd(&cnt[col[e]], 1);
    }
}

__global__ void k_dinv(const int* __restrict__ cnt, float* __restrict__ dinv, int n) {
    int i = blockIdx.x * blockDim.x + threadIdx.x;
    if (i < n) dinv[i] = rsqrtf((float)cnt[i] + 1.0f);   // +1 = self loop
}

// ---------------- build: 3-pass exclusive scan of cnt -> off ----------------
__global__ void k_scan1(const int* __restrict__ cnt, int* __restrict__ incl,
                        int* __restrict__ bsum, int n) {
    __shared__ int s[SCAN_B];
    int i = blockIdx.x * SCAN_B + threadIdx.x;
    int v = (i < n) ? cnt[i] : 0;
    s[threadIdx.x] = v;
    __syncthreads();
    #pragma unroll
    for (int d = 1; d < SCAN_B; d <<= 1) {
        int t = (threadIdx.x >= d) ? s[threadIdx.x - d] : 0;
        __syncthreads();
        s[threadIdx.x] += t;
        __syncthreads();
    }
    if (i < n) incl[i] = s[threadIdx.x];
    if (threadIdx.x == SCAN_B - 1) bsum[blockIdx.x] = s[SCAN_B - 1];
}

__global__ void k_scan2(int* __restrict__ bsum, int nb) {
    __shared__ int s[128];
    int tid = threadIdx.x;
    int v = (tid < nb) ? bsum[tid] : 0;
    s[tid] = v;
    __syncthreads();
    #pragma unroll
    for (int d = 1; d < 128; d <<= 1) {
        int t = (tid >= d) ? s[tid - d] : 0;
        __syncthreads();
        s[tid] += t;
        __syncthreads();
    }
    if (tid < nb) bsum[tid] = s[tid] - v;   // exclusive
}

__global__ void k_scan3(int* __restrict__ off, const int* __restrict__ cnt,
                        const int* __restrict__ bsum, int n) {
    int i = blockIdx.x * blockDim.x + threadIdx.x;
    if (i < n) off[i] = off[i] + bsum[i / SCAN_B] - cnt[i];  // incl -> excl global
}

// ---------------- build: bucket fill (interleaved payload) ----------------
__global__ void k_fill(const int* __restrict__ row, const int* __restrict__ col,
                       const int* __restrict__ off, int* __restrict__ fill,
                       const float* __restrict__ dinv,
                       int2* __restrict__ edge, int E) {
    int e = blockIdx.x * blockDim.x + threadIdx.x;
    if (e < E) {
        int c = col[e], r = row[e];
        int pos = off[c] + atomicAdd(&fill[c], 1);
        float nm = dinv[r] * dinv[c];
        edge[pos] = make_int2(r, __float_as_int(nm));
    }
}

// ---------------- tiled GEMM (FFMA2, packed operands): out[n,64] = H[n,K] @ W[K,64] ----
// 64x64 block tile, 256 threads. Thread (tr,tc) owns rows tr*4..tr*4+3 and
// cols {2tc, 2tc+1, 32+2tc, 32+2tc+1}. A tile stored transposed (row-pairs read
// packed via LDS.128); W tile stored pre-splatted as f32x2 doubles. Inner loop:
// 3 LDS.128 + 8 FFMA2 per kk (32 MACs) -> fma-pipe bound.
template <int K>
__global__ __launch_bounds__(256) void k_gemm(const float* __restrict__ H,
                                              const float* __restrict__ W,
                                              float* __restrict__ out, int n) {
    __shared__ __align__(16) float sHT[32][68];             // [kk][row], 8.7 KB
    __shared__ unsigned long long sW2[32 * 64];             // [kk][col] splatted, 16 KB
    const int tid  = threadIdx.x;
    const int row0 = blockIdx.x * 64;
    const int tc   = tid & 15;
    const int tr   = tid >> 4;

    unsigned long long acc[2][4] = {};   // [row-pair rp][col j]; rows tr*4+2rp{+0,+1}

    for (int k0 = 0; k0 < K; k0 += 32) {
        // sHT: warp reads 32 consecutive k of 4 rows (coalesced), stores transposed
        #pragma unroll
        for (int i = tid; i < 16 * 32; i += 256) {
            int r4 = i >> 5;          // row group (4 rows)
            int kk = i & 31;
            float v[4];
            #pragma unroll
            for (int j = 0; j < 4; j++) {
                int gr = row0 + r4 * 4 + j;
                v[j] = (gr < n) ? H[(size_t)gr * K + k0 + kk] : 0.0f;
            }
            *(float4*)&sHT[kk][r4 * 4] = make_float4(v[0], v[1], v[2], v[3]);
        }
        // sW2: splat each W element into a f32x2 double
        #pragma unroll
        for (int i = tid; i < 32 * 16; i += 256) {
            int kr  = i >> 4;
            int cc4 = (i & 15) * 4;
            float4 w = *(const float4*)(W + (size_t)(k0 + kr) * 64 + cc4);
            ulonglong2 p0 = make_ulonglong2(splat2(w.x), splat2(w.y));
            ulonglong2 p1 = make_ulonglong2(splat2(w.z), splat2(w.w));
            *(ulonglong2*)&sW2[kr * 64 + cc4]     = p0;
            *(ulonglong2*)&sW2[kr * 64 + cc4 + 2] = p1;
        }
        __syncthreads();

        #pragma unroll
        for (int kk = 0; kk < 32; kk++) {
            ulonglong2 a  = *(const ulonglong2*)&sHT[kk][tr * 4];            // {r0,r1},{r2,r3}
            ulonglong2 b0 = *(const ulonglong2*)&sW2[kk * 64 + 2 * tc];      // cols 2tc,2tc+1
            ulonglong2 b1 = *(const ulonglong2*)&sW2[kk * 64 + 32 + 2 * tc]; // cols 32+2tc,+1
            fma2(acc[0][0], a.x, b0.x);
            fma2(acc[0][1], a.x, b0.y);
            fma2(acc[0][2], a.x, b1.x);
            fma2(acc[0][3], a.x, b1.y);
            fma2(acc[1][0], a.y, b0.x);
            fma2(acc[1][1], a.y, b0.y);
            fma2(acc[1][2], a.y, b1.x);
            fma2(acc[1][3], a.y, b1.y);
        }
        __syncthreads();
    }

    #pragma unroll
    for (int rp = 0; rp < 2; rp++) {
        float lo[4], hi[4];
        #pragma unroll
        for (int j = 0; j < 4; j++) unpack2(acc[rp][j], lo[j], hi[j]);
        int gr = row0 + tr * 4 + rp * 2;
        if (gr < n) {
            *(float2*)(out + (size_t)gr * 64 + 2 * tc)      = make_float2(lo[0], lo[1]);
            *(float2*)(out + (size_t)gr * 64 + 32 + 2 * tc) = make_float2(lo[2], lo[3]);
        }
        if (gr + 1 < n) {
            *(float2*)(out + (size_t)(gr + 1) * 64 + 2 * tc)      = make_float2(hi[0], hi[1]);
            *(float2*)(out + (size_t)(gr + 1) * 64 + 32 + 2 * tc) = make_float2(hi[2], hi[3]);
        }
    }
}

// ---------------- pull-mode gather + self-loop + bias + relu (fused) ----------------
// 16 threads per destination node; lane owns one float4 column chunk.
// (src,nrm) pairs interleaved (one LDG.64/lane/chunk), double-buffered so the
// next chunk's index load overlaps this chunk's 16 gather loads. Two
// accumulator chains (even/odd k) halve the dependent-FFMA latency per chunk.
__global__ __launch_bounds__(256) void k_gather(
    const float* __restrict__ hw, const int* __restrict__ off,
    const int* __restrict__ cnt, const int2* __restrict__ edge,
    const float* __restrict__ dinv, const float* __restrict__ bias,
    float* __restrict__ out, int n)
{
    int g    = blockIdx.x * (blockDim.x >> 4) + (threadIdx.x >> 4);
    int lane = threadIdx.x & 15;
    if (g >= n) return;
    unsigned mask = 0xFFFFu << (threadIdx.x & 16);   // this half-warp

    // bias hoisted: no dependent load left in the epilogue
    float4 bv = *(const float4*)(bias + lane * 4);

    // self loop: hw[g] * dinv[g]^2
    float dv = dinv[g];
    float sl = dv * dv;
    float4 acc0 = *(const float4*)(hw + (size_t)g * HID + lane * 4);
    acc0.x *= sl; acc0.y *= sl; acc0.z *= sl; acc0.w *= sl;
    float4 acc1 = make_float4(0.f, 0.f, 0.f, 0.f);

    const int s = off[g];
    const int e = s + cnt[g];

    int2 pj = make_int2(0, 0);
    {
        int idx = s + lane;
        if (idx < e) pj = edge[idx];
    }

    for (int base = s; base < e; base += 16) {
        int2 cur = pj;
        int nidx = base + 16 + lane;
        pj = make_int2(0, 0);
        if (nidx < e) pj = edge[nidx];

        int m = e - base; if (m > 16) m = 16;
        #pragma unroll 4
        for (int k = 0; k < m; k++) {
            int   sk = __shfl_sync(mask, cur.x, k, 16);
            float nk = __int_as_float(__shfl_sync(mask, cur.y, k, 16));
            float4 v = *(const float4*)(hw + (size_t)sk * HID + lane * 4);
            if (k & 1) {
                acc1.x += nk * v.x; acc1.y += nk * v.y;
                acc1.z += nk * v.z; acc1.w += nk * v.w;
            } else {
                acc0.x += nk * v.x; acc0.y += nk * v.y;
                acc0.z += nk * v.z; acc0.w += nk * v.w;
            }
        }
    }

    acc0.x = fmaxf(acc0.x + acc1.x + bv.x, 0.f);
    acc0.y = fmaxf(acc0.y + acc1.y + bv.y, 0.f);
    acc0.z = fmaxf(acc0.z + acc1.z + bv.z, 0.f);
    acc0.w = fmaxf(acc0.w + acc1.w + bv.w, 0.f);
    *(float4*)(out + (size_t)g * HID + lane * 4) = acc0;
}

// ---------------- launch ----------------
extern "C" void kernel_launch(void* const* d_in, const int* in_sizes, int n_in,
                              void* d_out, int out_size) {
    const float* x  = (const float*)d_in[0];
    const int*   ei = (const int*)d_in[1];
    const float* W[5] = {(const float*)d_in[2], (const float*)d_in[4], (const float*)d_in[6],
                         (const float*)d_in[8], (const float*)d_in[10]};
    const float* b[5] = {(const float*)d_in[3], (const float*)d_in[5], (const float*)d_in[7],
                         (const float*)d_in[9], (const float*)d_in[11]};

    const int n = in_sizes[0] / 128;   // 100000
    const int E = in_sizes[1] / 2;     // 1600000
    const int* erow = ei;
    const int* ecol = ei + E;

    int *cnt, *fill, *off, *bsum;
    int2* edge;
    float *dinv, *hw, *h;
    cudaGetSymbolAddress((void**)&cnt,  g_cnt);
    cudaGetSymbolAddress((void**)&fill, g_fill);
    cudaGetSymbolAddress((void**)&off,  g_off);
    cudaGetSymbolAddress((void**)&bsum, g_bsum);
    cudaGetSymbolAddress((void**)&dinv, g_dinv);
    cudaGetSymbolAddress((void**)&edge, g_edge);
    cudaGetSymbolAddress((void**)&hw,   g_hw);
    cudaGetSymbolAddress((void**)&h,    g_h);

    const int TB = 256;
    const int ngrid = (n + TB - 1) / TB;
    const int egrid = (E + TB - 1) / TB;
    const int hgrid = (E / 4 + TB - 1) / TB + 1;   // int4 histogram
    const int nb    = (n + SCAN_B - 1) / SCAN_B;

    // ---- CSR build (once per forward) ----
    k_zero <<<ngrid, TB>>>(cnt, fill, n);
    k_hist <<<hgrid, TB>>>(ecol, cnt, E);
    k_dinv <<<ngrid, TB>>>(cnt, dinv, n);
    k_scan1<<<nb, SCAN_B>>>(cnt, off, bsum, n);
    k_scan2<<<1, 128>>>(bsum, nb);
    k_scan3<<<ngrid, TB>>>(off, cnt, bsum, n);
    k_fill <<<egrid, TB>>>(erow, ecol, off, fill, dinv, edge, E);

    // ---- 5 GCN layers ----
    const int gemm_grid   = (n + 63) / 64;
    const int gather_grid = (n * 16 + TB - 1) / TB;   // 16 threads per node

    for (int l = 0; l < 5; l++) {
        const float* h_in = (l == 0) ? x : h;
        if (l == 0) k_gemm<128><<<gemm_grid, 256>>>(h_in, W[l], hw, n);
        else        k_gemm< 64><<<gemm_grid, 256>>>(h_in, W[l], hw, n);

        float* dst = (l == 4) ? (float*)d_out : h;
        k_gather<<<gather_grid, TB>>>(hw, off, cnt, edge, dinv, b[l], dst, n);
    }
}